// round 7
// baseline (speedup 1.0000x reference)
#include <cuda_runtime.h>
#include <cstdint>

#define N_NODES 40000
#define N_EDGES 640000
#define D_FEAT  128

// Degree accumulator scratch (no cudaMalloc allowed).
__device__ float g_deg[N_NODES];

// ---------------------------------------------------------------------------
// Kernel 1: zero the output accumulator (d_out is poisoned 0xAA) and g_deg.
// ---------------------------------------------------------------------------
__global__ void zero_kernel(float4* __restrict__ out)
{
    int i = blockIdx.x * blockDim.x + threadIdx.x;
    const int n4 = N_NODES * (D_FEAT / 4);   // 1,280,000 float4
    if (i < n4) out[i] = make_float4(0.f, 0.f, 0.f, 0.f);
    if (i < N_NODES) g_deg[i] = 0.f;
}

// ---------------------------------------------------------------------------
// Kernel 2: one warp per edge.
//   Each lane loads one float4 of x[col] (32 lanes * 16B = 512B row, fully
//   coalesced), scales by adj_val, and issues a single vectorized
//   red.global.add.v4.f32 into out[row]. Lane 0 accumulates the degree.
//   x (20.5 MB) is L2-resident, so both gather and scatter hit L2.
// ---------------------------------------------------------------------------
__global__ void __launch_bounds__(256) edge_kernel(
    const float*  __restrict__ x,
    const int*    __restrict__ edge_rows,
    const int*    __restrict__ edge_cols,
    const float*  __restrict__ adj_vals,
    float*        __restrict__ out)
{
    const int warp_id = (blockIdx.x * blockDim.x + threadIdx.x) >> 5;
    const int lane    = threadIdx.x & 31;
    if (warp_id >= N_EDGES) return;

    // All lanes read the same address -> single broadcast wavefront.
    const int   r = edge_rows[warp_id];
    const int   c = edge_cols[warp_id];
    const float v = adj_vals[warp_id];

    const float4* src = reinterpret_cast<const float4*>(x + (size_t)c * D_FEAT) + lane;
    float4 m = *src;
    m.x *= v; m.y *= v; m.z *= v; m.w *= v;

    float* dst = out + (size_t)r * D_FEAT + lane * 4;
    asm volatile("red.global.add.v4.f32 [%0], {%1, %2, %3, %4};"
                 :: "l"(dst), "f"(m.x), "f"(m.y), "f"(m.z), "f"(m.w)
                 : "memory");

    if (lane == 0) atomicAdd(&g_deg[r], v);
}

// ---------------------------------------------------------------------------
// Kernel 3: out = (deg == 0 ? 0 : agg/deg) + bias   (bias added even at deg=0,
// matching the reference's where(...)+bias ordering).
// One thread per float4.
// ---------------------------------------------------------------------------
__global__ void finalize_kernel(float4* __restrict__ out,
                                const float4* __restrict__ bias4)
{
    int i = blockIdx.x * blockDim.x + threadIdx.x;
    const int n4 = N_NODES * (D_FEAT / 4);
    if (i >= n4) return;

    const int node = i >> 5;          // / (D_FEAT/4)
    const int f4   = i & 31;          // % (D_FEAT/4)

    const float d   = g_deg[node];
    const float inv = (d == 0.f) ? 0.f : 1.f / d;

    float4 a = out[i];
    float4 b = bias4[f4];
    a.x = a.x * inv + b.x;
    a.y = a.y * inv + b.y;
    a.z = a.z * inv + b.z;
    a.w = a.w * inv + b.w;
    out[i] = a;
}

// ---------------------------------------------------------------------------
extern "C" void kernel_launch(void* const* d_in, const int* in_sizes, int n_in,
                              void* d_out, int out_size)
{
    const float* x         = (const float*)d_in[0];
    const int*   edge_rows = (const int*)  d_in[1];
    const int*   edge_cols = (const int*)  d_in[2];
    const float* adj_vals  = (const float*)d_in[3];
    const float* bias      = (const float*)d_in[4];
    float*       out       = (float*)d_out;

    (void)in_sizes; (void)n_in; (void)out_size;

    const int n4 = N_NODES * (D_FEAT / 4);            // 1,280,000

    // 1. zero accumulators
    {
        int threads = 256;
        int blocks  = (n4 + threads - 1) / threads;   // 5000
        zero_kernel<<<blocks, threads>>>((float4*)out);
    }

    // 2. edge scatter: one warp per edge, 8 warps per block
    {
        int threads = 256;
        int blocks  = (N_EDGES * 32 + threads - 1) / threads;  // 80,000
        edge_kernel<<<blocks, threads>>>(x, edge_rows, edge_cols, adj_vals, out);
    }

    // 3. normalize + bias
    {
        int threads = 256;
        int blocks  = (n4 + threads - 1) / threads;   // 5000
        finalize_kernel<<<blocks, threads>>>((float4*)out, (const float4*)bias);
    }
}